// round 5
// baseline (speedup 1.0000x reference)
#include <cuda_runtime.h>
#include <math.h>
#include <float.h>

#define NN 100000
#define EE 400000
#define GG 4096
#define EMB 128
#define LN2F 0.6931471805599453f

// ---------------- scratch ----------------
__device__ float g_ha  [NN * EMB];
__device__ float g_hb  [NN * EMB];
__device__ float g_PQ  [NN * 2 * EMB];   // [P | Q], pitch 256
__device__ float g_X   [NN * 2 * EMB];   // [U | T], pitch 256
__device__ float g_comb[EMB * 2 * EMB];  // [W1-W2 | W2]  (128 x 256)
__device__ float g_wcat[2 * EMB * EMB];  // [W_msg ; W_edge] (256 x 128)
__device__ int   g_deg [NN];
__device__ int   g_off [NN + 1];
__device__ int   g_fill[NN];
__device__ int   g_bsumA[128];
__device__ int   g_boff [128];
__device__ int   g_csr_src[EE];
__device__ int   g_csr_eid[EE];
__device__ int   g_gstart[GG + 1];

__device__ __forceinline__ float sp(float x) {
    return fmaxf(x, 0.f) + log1pf(expf(-fabsf(x)));
}
__device__ __forceinline__ float4 max4(float4 a, float4 b) {
    return make_float4(fmaxf(a.x,b.x), fmaxf(a.y,b.y), fmaxf(a.z,b.z), fmaxf(a.w,b.w));
}

// ---------------- setup ----------------
__global__ void embed_sp_kernel(const float* __restrict__ emb, const int* __restrict__ ids,
                                float* __restrict__ out, int rows) {
    int t = blockIdx.x * blockDim.x + threadIdx.x;
    if (t >= rows * 32) return;
    int n = t >> 5, l = t & 31;
    float4 v = ((const float4*)emb)[ids[n] * 32 + l];
    ((float4*)out)[(size_t)n * 32 + l] = make_float4(sp(v.x), sp(v.y), sp(v.z), sp(v.w));
}

__global__ void count_deg_kernel(const int* __restrict__ dst) {
    int e = blockIdx.x * blockDim.x + threadIdx.x;
    if (e < EE) atomicAdd(&g_deg[dst[e]], 1);
}

__global__ void scan1_kernel() {
    __shared__ int s[1024];
    int t = threadIdx.x;
    int n = blockIdx.x * 1024 + t;
    int v = (n < NN) ? g_deg[n] : 0;
    s[t] = v;
    __syncthreads();
    for (int off = 1; off < 1024; off <<= 1) {
        int add = (t >= off) ? s[t - off] : 0;
        __syncthreads();
        s[t] += add;
        __syncthreads();
    }
    if (n < NN) g_off[n] = s[t] - v;
    if (t == 1023) g_bsumA[blockIdx.x] = s[1023];
}

__global__ void scan2_kernel(int nblk) {
    if (threadIdx.x == 0) {
        int run = 0;
        for (int i = 0; i < nblk; i++) { int v = g_bsumA[i]; g_boff[i] = run; run += v; }
    }
}

__global__ void scan3_kernel() {
    int n = blockIdx.x * blockDim.x + threadIdx.x;
    if (n < NN) g_off[n] += g_boff[n >> 10];
    if (n == 0) g_off[NN] = EE;
}

__global__ void fill_csr_kernel(const int* __restrict__ src, const int* __restrict__ dst) {
    int e = blockIdx.x * blockDim.x + threadIdx.x;
    if (e >= EE) return;
    int d = dst[e];
    int pos = atomicAdd(&g_fill[d], 1);
    int idx = g_off[d] + pos;
    g_csr_src[idx] = src[e];
    g_csr_eid[idx] = e;
}

__global__ void bounds_kernel(const int* __restrict__ batch) {
    int n = blockIdx.x * blockDim.x + threadIdx.x;
    if (n >= NN) return;
    int b = batch[n];
    int prev = (n == 0) ? -1 : batch[n - 1];
    for (int g = prev + 1; g <= b; g++) g_gstart[g] = n;
    if (n == NN - 1)
        for (int g = b + 1; g <= GG; g++) g_gstart[g] = NN;
}

__global__ void build_comb_kernel(const float* __restrict__ Wb) {
    int idx = blockIdx.x * blockDim.x + threadIdx.x;
    if (idx >= EMB * 2 * EMB) return;
    int k = idx >> 8, j = idx & 255;
    float v;
    if (j < EMB) v = Wb[k * EMB + j] - Wb[(k + EMB) * EMB + j];
    else         v = Wb[(k + EMB) * EMB + (j - EMB)];
    g_comb[k * 256 + j] = v;
}

__global__ void build_wcat_kernel(const float* __restrict__ Wm, const float* __restrict__ We) {
    int idx = blockIdx.x * blockDim.x + threadIdx.x;
    if (idx >= 2 * EMB * EMB) return;
    int r = idx >> 7, c = idx & 127;
    g_wcat[idx] = (r < EMB) ? Wm[r * EMB + c] : We[(r - EMB) * EMB + c];
}

// ---------------- SIMT fp32 GEMM, double-buffered smem ----------------
// C[M x Nc] = A[M x K] @ W[K x Nc]; 128x128 tile, 256 threads, 8x8 microtile.
// Fused epilogue if bmsg != null.
__global__ __launch_bounds__(256)
void gemm_simt(const float* __restrict__ A, const float* __restrict__ W,
               float* __restrict__ C, int M, int K, int Nc,
               const float* __restrict__ bmsg, const float* __restrict__ bedge,
               const int* __restrict__ degp, float* __restrict__ out2) {
    __shared__ float sA[2][16][132];   // [stage][k][m]
    __shared__ float sB[2][16][132];   // [stage][k][n]

    const int tid  = threadIdx.x;
    const int lane = tid & 31;
    const int warp = tid >> 5;
    const int tr   = lane >> 3, tc = lane & 7;
    const int wm   = warp >> 1, wn = warp & 1;
    const int bm   = blockIdx.x * 128;
    const int bn   = blockIdx.y * 128;
    const int mrow = wm * 32 + tr * 8;
    const int ncol = wn * 64 + tc * 8;

    float acc[8][8];
#pragma unroll
    for (int i = 0; i < 8; i++)
#pragma unroll
        for (int j = 0; j < 8; j++) acc[i][j] = 0.f;

    const int a_row0 = tid >> 2;
    const int a_c4   = tid & 3;
    const int b_k0   = tid >> 5;
    const int b_n4   = tid & 31;
    const int chunks = K >> 4;

    // stage 0 fill
    {
#pragma unroll
        for (int i = 0; i < 2; i++) {
            int gr = bm + a_row0 + i * 64;
            float4 av = (gr < M) ? *(const float4*)&A[(size_t)gr * K + a_c4 * 4]
                                 : make_float4(0.f, 0.f, 0.f, 0.f);
            const float* v = (const float*)&av;
#pragma unroll
            for (int j = 0; j < 4; j++) sA[0][a_c4 * 4 + j][a_row0 + i * 64] = v[j];
            *(float4*)&sB[0][b_k0 + i * 8][b_n4 * 4] =
                *(const float4*)&W[(size_t)(b_k0 + i * 8) * Nc + bn + b_n4 * 4];
        }
    }
    __syncthreads();

    for (int ch = 0; ch < chunks; ch++) {
        int cur = ch & 1, nxt = cur ^ 1;
        // prefetch next chunk into regs
        float4 abuf[2], bbuf[2];
        if (ch < chunks - 1) {
            int kb = (ch + 1) * 16;
#pragma unroll
            for (int i = 0; i < 2; i++) {
                int gr = bm + a_row0 + i * 64;
                abuf[i] = (gr < M) ? *(const float4*)&A[(size_t)gr * K + kb + a_c4 * 4]
                                   : make_float4(0.f, 0.f, 0.f, 0.f);
                bbuf[i] = *(const float4*)&W[(size_t)(kb + b_k0 + i * 8) * Nc + bn + b_n4 * 4];
            }
        }
        // compute on cur
#pragma unroll
        for (int k = 0; k < 16; k++) {
            float a[8], b[8];
            *(float4*)&a[0] = *(const float4*)&sA[cur][k][mrow];
            *(float4*)&a[4] = *(const float4*)&sA[cur][k][mrow + 4];
            *(float4*)&b[0] = *(const float4*)&sB[cur][k][ncol];
            *(float4*)&b[4] = *(const float4*)&sB[cur][k][ncol + 4];
#pragma unroll
            for (int i = 0; i < 8; i++)
#pragma unroll
                for (int j = 0; j < 8; j++) acc[i][j] += a[i] * b[j];
        }
        // stage next
        if (ch < chunks - 1) {
#pragma unroll
            for (int i = 0; i < 2; i++) {
                const float* v = (const float*)&abuf[i];
#pragma unroll
                for (int j = 0; j < 4; j++) sA[nxt][a_c4 * 4 + j][a_row0 + i * 64] = v[j];
                *(float4*)&sB[nxt][b_k0 + i * 8][b_n4 * 4] = bbuf[i];
            }
            __syncthreads();
        }
    }

    // epilogue
    if (!bmsg) {
#pragma unroll
        for (int i = 0; i < 8; i++) {
            int gr = bm + mrow + i;
            if (gr < M) {
                *(float4*)&C[(size_t)gr * Nc + bn + ncol]     = *(float4*)&acc[i][0];
                *(float4*)&C[(size_t)gr * Nc + bn + ncol + 4] = *(float4*)&acc[i][4];
            }
        }
    } else {
        float bs[8];
#pragma unroll
        for (int j = 0; j < 8; j++) {
            int gc = bn + ncol + j;
            bs[j] = bmsg[gc] + bedge[gc];
        }
#pragma unroll
        for (int i = 0; i < 8; i++) {
            int gr = bm + mrow + i;
            if (gr < M) {
                float dg = (float)degp[gr];
                float4 o0 = *(const float4*)&C[(size_t)gr * Nc + bn + ncol];
                float4 o1 = *(const float4*)&C[(size_t)gr * Nc + bn + ncol + 4];
                float4 v0 = make_float4(sp(acc[i][0] + dg * bs[0] + o0.x),
                                        sp(acc[i][1] + dg * bs[1] + o0.y),
                                        sp(acc[i][2] + dg * bs[2] + o0.z),
                                        sp(acc[i][3] + dg * bs[3] + o0.w));
                float4 v1 = make_float4(sp(acc[i][4] + dg * bs[4] + o1.x),
                                        sp(acc[i][5] + dg * bs[5] + o1.y),
                                        sp(acc[i][6] + dg * bs[6] + o1.z),
                                        sp(acc[i][7] + dg * bs[7] + o1.w));
                *(float4*)&C[(size_t)gr * Nc + bn + ncol]     = v0;
                *(float4*)&C[(size_t)gr * Nc + bn + ncol + 4] = v1;
                if (out2) {
                    *(float4*)&out2[(size_t)gr * Nc + bn + ncol]     = v0;
                    *(float4*)&out2[(size_t)gr * Nc + bn + ncol + 4] = v1;
                }
            }
        }
    }
}

// ---------------- CSR aggregations (warp per node, no atomics) ----------------
#define MAXPREF 16
__global__ void agg_max_kernel(const float* __restrict__ b_bond, float* __restrict__ out2) {
    int nid = blockIdx.x * 8 + (threadIdx.x >> 5);
    if (nid >= NN) return;
    int l = threadIdx.x & 31;
    int o0 = g_off[nid], o1 = g_off[nid + 1];
    const float4* PQ4 = (const float4*)g_PQ;
    float4 res;
    if (o1 > o0) {
        int cnt = o1 - o0;
        float4 m = make_float4(-FLT_MAX, -FLT_MAX, -FLT_MAX, -FLT_MAX);
        int i = 0;
        while (i < cnt) {
            int batch = min(cnt - i, MAXPREF);
            int idxs[MAXPREF];
#pragma unroll 4
            for (int j = 0; j < batch; j++) idxs[j] = g_csr_src[o0 + i + j];
#pragma unroll 4
            for (int j = 0; j < batch; j++)
                m = max4(m, PQ4[(size_t)idxs[j] * 64 + 32 + l]);
            i += batch;
        }
        float4 p  = PQ4[(size_t)nid * 64 + l];
        float4 bb = ((const float4*)b_bond)[l];
        res = make_float4(sp(m.x + p.x + bb.x), sp(m.y + p.y + bb.y),
                          sp(m.z + p.z + bb.z), sp(m.w + p.w + bb.w));
    } else {
        res = make_float4(LN2F, LN2F, LN2F, LN2F);
    }
    ((float4*)g_hb)[(size_t)nid * 32 + l] = res;
    if (out2) ((float4*)out2)[(size_t)nid * 32 + l] = res;
}

__global__ void agg_sum_kernel() {
    int nid = blockIdx.x * 8 + (threadIdx.x >> 5);
    if (nid >= NN) return;
    int l = threadIdx.x & 31;
    int o0 = g_off[nid], o1 = g_off[nid + 1];
    const float4* ha4 = (const float4*)g_ha;
    const float4* hb4 = (const float4*)g_hb;
    float4 u = make_float4(0.f, 0.f, 0.f, 0.f);
    float4 t = make_float4(0.f, 0.f, 0.f, 0.f);
    float cge = 0.f;
    int cnt = o1 - o0;
    int i = 0;
    while (i < cnt) {
        int batch = min(cnt - i, MAXPREF);
        int ss[MAXPREF], es[MAXPREF];
#pragma unroll 4
        for (int j = 0; j < batch; j++) {
            ss[j] = g_csr_src[o0 + i + j];
            es[j] = g_csr_eid[o0 + i + j];
        }
#pragma unroll 4
        for (int j = 0; j < batch; j++) {
            float4 av = ha4[(size_t)ss[j] * 32 + l];
            u.x += av.x; u.y += av.y; u.z += av.z; u.w += av.w;
            if (es[j] < NN) {
                float4 bv = hb4[(size_t)es[j] * 32 + l];
                t.x += bv.x; t.y += bv.y; t.z += bv.z; t.w += bv.w;
            } else cge += 1.f;
        }
        i += batch;
    }
    float c = cge * LN2F;
    t.x += c; t.y += c; t.z += c; t.w += c;
    float4* X4 = (float4*)g_X;
    X4[(size_t)nid * 64 + l]      = u;
    X4[(size_t)nid * 64 + 32 + l] = t;
}

// ---------------- fused pool + readout ----------
__global__ void pool_readout_kernel(const float* __restrict__ Wr1, const float* __restrict__ br1,
                                    const float* __restrict__ Wr2, const float* __restrict__ br2,
                                    const float* __restrict__ Wr3, const float* __restrict__ br3,
                                    float* __restrict__ out) {
    __shared__ float pv[128];
    __shared__ float h1[64];
    __shared__ float h2[64];
    __shared__ float red[2];
    int g = blockIdx.x;
    int t = threadIdx.x;
    int s = g_gstart[g], e = g_gstart[g + 1];
    float sum = 0.f;
    for (int n = s; n < e; n++) sum += g_ha[(size_t)n * 128 + t];
    pv[t] = sum;
    __syncthreads();
    if (t < 64) {
        float a1 = br1[t];
#pragma unroll 8
        for (int k = 0; k < 128; k++) a1 += pv[k] * Wr1[k * 64 + t];
        h1[t] = sp(a1);
    }
    __syncthreads();
    if (t < 64) {
        float a2 = br2[t];
#pragma unroll 8
        for (int k = 0; k < 64; k++) a2 += h1[k] * Wr2[k * 64 + t];
        h2[t] = sp(a2);
    }
    __syncthreads();
    if (t < 64) {
        float v = h2[t] * Wr3[t];
#pragma unroll
        for (int o = 16; o > 0; o >>= 1) v += __shfl_down_sync(0xffffffffu, v, o);
        if ((t & 31) == 0) red[t >> 5] = v;
    }
    __syncthreads();
    if (t == 0) out[g] = red[0] + red[1] + br3[0];
}

__global__ void tail_hb_kernel(float* __restrict__ out_hb) {
    int t = blockIdx.x * blockDim.x + threadIdx.x;
    if (t >= (EE - NN) * 32) return;
    ((float4*)out_hb)[(size_t)NN * 32 + t] = make_float4(LN2F, LN2F, LN2F, LN2F);
}

// ---------------- launch ----------------
extern "C" void kernel_launch(void* const* d_in, const int* in_sizes, int n_in,
                              void* d_out, int out_size) {
    const int*   x_ids      = (const int*)d_in[0];
    const int*   edge_attr  = (const int*)d_in[1];
    const int*   edge_index = (const int*)d_in[2];
    const int*   batch      = (const int*)d_in[3];
    const float* emb_atom   = (const float*)d_in[4];
    const float* emb_bond   = (const float*)d_in[5];
    const float* W_bond     = (const float*)d_in[6];
    const float* b_bond     = (const float*)d_in[7];
    const float* W_msg      = (const float*)d_in[8];
    const float* b_msg      = (const float*)d_in[9];
    const float* W_edge     = (const float*)d_in[10];
    const float* b_edge     = (const float*)d_in[11];
    const float* W_r1       = (const float*)d_in[12];
    const float* b_r1       = (const float*)d_in[13];
    const float* W_r2       = (const float*)d_in[14];
    const float* b_r2       = (const float*)d_in[15];
    const float* W_r3       = (const float*)d_in[16];
    const float* b_r3       = (const float*)d_in[17];

    const int* src = edge_index;
    const int* dst = edge_index + EE;

    float* out_g  = (float*)d_out;
    float* out_ha = out_g + GG;
    float* out_hb = out_ha + (size_t)NN * EMB;

    void *p_deg, *p_fill, *p_ha, *p_hb, *p_PQ, *p_X, *p_comb, *p_wcat;
    cudaGetSymbolAddress(&p_deg,  g_deg);
    cudaGetSymbolAddress(&p_fill, g_fill);
    cudaGetSymbolAddress(&p_ha,   g_ha);
    cudaGetSymbolAddress(&p_hb,   g_hb);
    cudaGetSymbolAddress(&p_PQ,   g_PQ);
    cudaGetSymbolAddress(&p_X,    g_X);
    cudaGetSymbolAddress(&p_comb, g_comb);
    cudaGetSymbolAddress(&p_wcat, g_wcat);

    const int T = 256;
    int blk_n32 = (NN * 32 + T - 1) / T;
    int blk_n   = (NN + T - 1) / T;
    int blk_e   = (EE + T - 1) / T;
    int blk_w   = (NN + 7) / 8;
    int gm128   = (NN + 127) / 128;
    int nblk_scan = (NN + 1023) / 1024;

    // --- setup A (launches 1-5), then first GEMM at launch slot 6 for ncu -s 5 ---
    cudaMemsetAsync(p_deg,  0, NN * sizeof(int));                       // 1
    cudaMemsetAsync(p_fill, 0, NN * sizeof(int));                       // 2
    embed_sp_kernel<<<blk_n32, T>>>(emb_atom, x_ids, (float*)p_ha, NN); // 3
    embed_sp_kernel<<<blk_n32, T>>>(emb_bond, edge_attr, (float*)p_hb, NN); // 4
    build_comb_kernel<<<(EMB * 2 * EMB + T - 1) / T, T>>>(W_bond);      // 5

    dim3 gr1(gm128, 2);
    gemm_simt<<<gr1, T>>>((const float*)p_hb, (const float*)p_comb, (float*)p_PQ,
                          NN, 128, 256, nullptr, nullptr, nullptr, nullptr); // 6 <- profiled

    // --- setup B (independent of GEMM) ---
    count_deg_kernel<<<blk_e, T>>>(dst);
    scan1_kernel<<<nblk_scan, 1024>>>();
    scan2_kernel<<<1, 32>>>(nblk_scan);
    scan3_kernel<<<blk_n, T>>>();
    fill_csr_kernel<<<blk_e, T>>>(src, dst);
    bounds_kernel<<<blk_n, T>>>(batch);
    build_wcat_kernel<<<(2 * EMB * EMB + T - 1) / T, T>>>(W_msg, W_edge);

    for (int pass = 0; pass < 2; pass++) {
        bool last = (pass == 1);
        if (pass > 0) {
            gemm_simt<<<gr1, T>>>((const float*)p_hb, (const float*)p_comb, (float*)p_PQ,
                                  NN, 128, 256, nullptr, nullptr, nullptr, nullptr);
        }
        agg_max_kernel<<<blk_w, T>>>(b_bond, last ? out_hb : nullptr);
        agg_sum_kernel<<<blk_w, T>>>();
        dim3 gr2(gm128, 1);
        gemm_simt<<<gr2, T>>>((const float*)p_X, (const float*)p_wcat, (float*)p_ha,
                              NN, 256, 128, b_msg, b_edge, (const int*)p_deg,
                              last ? out_ha : nullptr);
    }

    pool_readout_kernel<<<GG, 128>>>(W_r1, b_r1, W_r2, b_r2, W_r3, b_r3, out_g);
    tail_hb_kernel<<<((EE - NN) * 32 + T - 1) / T, T>>>(out_hb);
}

// round 7
// speedup vs baseline: 1.0199x; 1.0199x over previous
#include <cuda_runtime.h>
#include <math.h>
#include <float.h>

#define NN 100000
#define EE 400000
#define GG 4096
#define EMB 128
#define LN2F 0.6931471805599453f

// ---------------- scratch ----------------
__device__ float g_ha  [NN * EMB];
__device__ float g_hb  [NN * EMB];
__device__ float g_PQ  [NN * 2 * EMB];   // [P | Q], pitch 256
__device__ float g_X   [NN * 2 * EMB];   // [U | T], pitch 256
__device__ float g_comb[EMB * 2 * EMB];  // [W1-W2 | W2]  (128 x 256)
__device__ float g_wcat[2 * EMB * EMB];  // [W_msg ; W_edge] (256 x 128)
__device__ int   g_deg [NN];
__device__ int   g_off [NN + 1];
__device__ int   g_fill[NN];
__device__ int   g_bsumA[128];
__device__ int   g_boff [128];
__device__ int   g_csr_src[EE];
__device__ int   g_csr_eid[EE];
__device__ int   g_gstart[GG + 1];

__device__ __forceinline__ float sp(float x) {
    return fmaxf(x, 0.f) + log1pf(expf(-fabsf(x)));
}
__device__ __forceinline__ float4 max4(float4 a, float4 b) {
    return make_float4(fmaxf(a.x,b.x), fmaxf(a.y,b.y), fmaxf(a.z,b.z), fmaxf(a.w,b.w));
}
__device__ __forceinline__ float tf32_rna(float x) {
    unsigned r; asm("cvt.rna.tf32.f32 %0, %1;" : "=r"(r) : "f"(x));
    return __uint_as_float(r);
}
__device__ __forceinline__ void mma_tf32(float* d, const unsigned* a, const unsigned* b) {
    asm volatile(
        "mma.sync.aligned.m16n8k8.row.col.f32.tf32.tf32.f32 "
        "{%0,%1,%2,%3}, {%4,%5,%6,%7}, {%8,%9}, {%0,%1,%2,%3};\n"
        : "+f"(d[0]), "+f"(d[1]), "+f"(d[2]), "+f"(d[3])
        : "r"(a[0]), "r"(a[1]), "r"(a[2]), "r"(a[3]), "r"(b[0]), "r"(b[1]));
}
__device__ __forceinline__ float2 hl_split(float x) {
    float hi = tf32_rna(x);
    float lo = tf32_rna(x - hi);
    return make_float2(hi, lo);
}

// ---------------- setup ----------------
__global__ void embed_sp_kernel(const float* __restrict__ emb, const int* __restrict__ ids,
                                float* __restrict__ out, int rows) {
    int t = blockIdx.x * blockDim.x + threadIdx.x;
    if (t >= rows * 32) return;
    int n = t >> 5, l = t & 31;
    float4 v = ((const float4*)emb)[ids[n] * 32 + l];
    ((float4*)out)[(size_t)n * 32 + l] = make_float4(sp(v.x), sp(v.y), sp(v.z), sp(v.w));
}

__global__ void count_deg_kernel(const int* __restrict__ dst) {
    int e = blockIdx.x * blockDim.x + threadIdx.x;
    if (e < EE) atomicAdd(&g_deg[dst[e]], 1);
}

__global__ void scan1_kernel() {
    __shared__ int s[1024];
    int t = threadIdx.x;
    int n = blockIdx.x * 1024 + t;
    int v = (n < NN) ? g_deg[n] : 0;
    s[t] = v;
    __syncthreads();
    for (int off = 1; off < 1024; off <<= 1) {
        int add = (t >= off) ? s[t - off] : 0;
        __syncthreads();
        s[t] += add;
        __syncthreads();
    }
    if (n < NN) g_off[n] = s[t] - v;
    if (t == 1023) g_bsumA[blockIdx.x] = s[1023];
}

__global__ void scan2_kernel(int nblk) {
    if (threadIdx.x == 0) {
        int run = 0;
        for (int i = 0; i < nblk; i++) { int v = g_bsumA[i]; g_boff[i] = run; run += v; }
    }
}

__global__ void scan3_kernel() {
    int n = blockIdx.x * blockDim.x + threadIdx.x;
    if (n < NN) g_off[n] += g_boff[n >> 10];
    if (n == 0) g_off[NN] = EE;
}

__global__ void fill_csr_kernel(const int* __restrict__ src, const int* __restrict__ dst) {
    int e = blockIdx.x * blockDim.x + threadIdx.x;
    if (e >= EE) return;
    int d = dst[e];
    int pos = atomicAdd(&g_fill[d], 1);
    int idx = g_off[d] + pos;
    g_csr_src[idx] = src[e];
    g_csr_eid[idx] = e;
}

__global__ void bounds_kernel(const int* __restrict__ batch) {
    int n = blockIdx.x * blockDim.x + threadIdx.x;
    if (n >= NN) return;
    int b = batch[n];
    int prev = (n == 0) ? -1 : batch[n - 1];
    for (int g = prev + 1; g <= b; g++) g_gstart[g] = n;
    if (n == NN - 1)
        for (int g = b + 1; g <= GG; g++) g_gstart[g] = NN;
}

__global__ void build_comb_kernel(const float* __restrict__ Wb) {
    int idx = blockIdx.x * blockDim.x + threadIdx.x;
    if (idx >= EMB * 2 * EMB) return;
    int k = idx >> 8, j = idx & 255;
    float v;
    if (j < EMB) v = Wb[k * EMB + j] - Wb[(k + EMB) * EMB + j];
    else         v = Wb[(k + EMB) * EMB + (j - EMB)];
    g_comb[k * 256 + j] = v;
}

__global__ void build_wcat_kernel(const float* __restrict__ Wm, const float* __restrict__ We) {
    int idx = blockIdx.x * blockDim.x + threadIdx.x;
    if (idx >= 2 * EMB * EMB) return;
    int r = idx >> 7, c = idx & 127;
    g_wcat[idx] = (r < EMB) ? Wm[r * EMB + c] : We[(r - EMB) * EMB + c];
}

// ---------------- 3xTF32 tensor-core GEMM ----------------
// C[M x Nc] = A[M x K] @ W[K x Nc]; 128x128 block tile, 256 threads.
// 8 warps as 2(m) x 4(n): warp tile 64x32 = mma m16n8k8 grid 4x4.
// smem float2(hi,lo); sA pitch 20, sB pitch 132 -> conflict-free fragment LDS.64.
// Optional fused epilogue when bmsg != null.
__global__ __launch_bounds__(256)
void gemm_tc(const float* __restrict__ A, const float* __restrict__ W,
             float* __restrict__ C, int M, int K, int Nc,
             const float* __restrict__ bmsg, const float* __restrict__ bedge,
             const int* __restrict__ degp, float* __restrict__ out2) {
    __shared__ float2 sA[128][20];   // [row][k]
    __shared__ float2 sB[16][132];   // [k][n]

    const int tid  = threadIdx.x;
    const int lane = tid & 31;
    const int warp = tid >> 5;
    const int g    = lane >> 2;
    const int c    = lane & 3;
    const int wm   = warp >> 2;      // 0..1
    const int wn   = warp & 3;       // 0..3
    const int bm   = blockIdx.x * 128;
    const int bn   = blockIdx.y * 128;

    float acc[4][4][4];
#pragma unroll
    for (int mf = 0; mf < 4; mf++)
#pragma unroll
        for (int nf = 0; nf < 4; nf++)
#pragma unroll
            for (int i = 0; i < 4; i++) acc[mf][nf][i] = 0.f;

    // staging assignment
    const int ar  = tid >> 1;          // A row 0..127
    const int aq  = (tid & 1) * 2;     // quad base (k quads {0,1} or {2,3})
    const int bk  = tid & 15;          // B k-row 0..15
    const int bn0 = (tid >> 4) * 8;    // B n base (8 cols per thread)

    const int chunks = K >> 4;
    float4 abuf[2], bbuf[2];

    // prologue: load chunk 0
#pragma unroll
    for (int q = 0; q < 2; q++) {
        int kq = (aq + q) * 4;
        abuf[q] = (bm + ar < M) ? *(const float4*)&A[(size_t)(bm + ar) * K + kq]
                                : make_float4(0.f, 0.f, 0.f, 0.f);
        bbuf[q] = *(const float4*)&W[(size_t)bk * Nc + bn + bn0 + q * 4];
    }

    for (int ch = 0; ch < chunks; ch++) {
        // store staged chunk to smem (hi/lo split)
#pragma unroll
        for (int q = 0; q < 2; q++) {
            int kq = (aq + q) * 4;
            float2 p0 = hl_split(abuf[q].x), p1 = hl_split(abuf[q].y);
            float2 p2 = hl_split(abuf[q].z), p3 = hl_split(abuf[q].w);
            *(float4*)&sA[ar][kq]     = make_float4(p0.x, p0.y, p1.x, p1.y);
            *(float4*)&sA[ar][kq + 2] = make_float4(p2.x, p2.y, p3.x, p3.y);
            int nq = bn0 + q * 4;
            float2 r0 = hl_split(bbuf[q].x), r1 = hl_split(bbuf[q].y);
            float2 r2 = hl_split(bbuf[q].z), r3 = hl_split(bbuf[q].w);
            *(float4*)&sB[bk][nq]     = make_float4(r0.x, r0.y, r1.x, r1.y);
            *(float4*)&sB[bk][nq + 2] = make_float4(r2.x, r2.y, r3.x, r3.y);
        }
        __syncthreads();

        // prefetch next chunk (latency hidden by mma block)
        if (ch < chunks - 1) {
            int kb = (ch + 1) * 16;
#pragma unroll
            for (int q = 0; q < 2; q++) {
                int kq = kb + (aq + q) * 4;
                abuf[q] = (bm + ar < M) ? *(const float4*)&A[(size_t)(bm + ar) * K + kq]
                                        : make_float4(0.f, 0.f, 0.f, 0.f);
                bbuf[q] = *(const float4*)&W[(size_t)(kb + bk) * Nc + bn + bn0 + q * 4];
            }
        }

        // compute 2 k8 steps
#pragma unroll
        for (int ks = 0; ks < 16; ks += 8) {
            unsigned ah[4][4], al[4][4];
#pragma unroll
            for (int mf = 0; mf < 4; mf++) {
                int r0 = wm * 64 + mf * 16 + g;
                float2 a0 = sA[r0][ks + c];
                float2 a1 = sA[r0 + 8][ks + c];
                float2 a2 = sA[r0][ks + c + 4];
                float2 a3 = sA[r0 + 8][ks + c + 4];
                ah[mf][0] = __float_as_uint(a0.x); al[mf][0] = __float_as_uint(a0.y);
                ah[mf][1] = __float_as_uint(a1.x); al[mf][1] = __float_as_uint(a1.y);
                ah[mf][2] = __float_as_uint(a2.x); al[mf][2] = __float_as_uint(a2.y);
                ah[mf][3] = __float_as_uint(a3.x); al[mf][3] = __float_as_uint(a3.y);
            }
#pragma unroll
            for (int nf = 0; nf < 4; nf++) {
                int n0 = wn * 32 + nf * 8 + g;
                float2 b0 = sB[ks + c][n0];
                float2 b1 = sB[ks + c + 4][n0];
                unsigned bh[2] = {__float_as_uint(b0.x), __float_as_uint(b1.x)};
                unsigned bl[2] = {__float_as_uint(b0.y), __float_as_uint(b1.y)};
#pragma unroll
                for (int mf = 0; mf < 4; mf++) {
                    mma_tf32(acc[mf][nf], ah[mf], bh);
                    mma_tf32(acc[mf][nf], al[mf], bh);
                    mma_tf32(acc[mf][nf], ah[mf], bl);
                }
            }
        }
        __syncthreads();
    }

    // epilogue: acc regs map to (row = base+g [+8], col = base+2c [+1])
    if (!bmsg) {
#pragma unroll
        for (int mf = 0; mf < 4; mf++) {
            int r0 = bm + wm * 64 + mf * 16 + g;
#pragma unroll
            for (int nf = 0; nf < 4; nf++) {
                int col = bn + wn * 32 + nf * 8 + c * 2;
                if (r0 < M)
                    *(float2*)&C[(size_t)r0 * Nc + col] = make_float2(acc[mf][nf][0], acc[mf][nf][1]);
                if (r0 + 8 < M)
                    *(float2*)&C[(size_t)(r0 + 8) * Nc + col] = make_float2(acc[mf][nf][2], acc[mf][nf][3]);
            }
        }
    } else {
        float bsv[4][2];
#pragma unroll
        for (int nf = 0; nf < 4; nf++) {
            int col = bn + wn * 32 + nf * 8 + c * 2;
            bsv[nf][0] = bmsg[col] + bedge[col];
            bsv[nf][1] = bmsg[col + 1] + bedge[col + 1];
        }
#pragma unroll
        for (int mf = 0; mf < 4; mf++) {
            int r0 = bm + wm * 64 + mf * 16 + g;
#pragma unroll
            for (int rr = 0; rr < 2; rr++) {
                int row = r0 + rr * 8;
                if (row < M) {
                    float dg = (float)degp[row];
#pragma unroll
                    for (int nf = 0; nf < 4; nf++) {
                        int col = bn + wn * 32 + nf * 8 + c * 2;
                        float x0 = acc[mf][nf][rr * 2 + 0];
                        float x1 = acc[mf][nf][rr * 2 + 1];
                        float2 old = *(const float2*)&C[(size_t)row * Nc + col];
                        float v0 = sp(x0 + dg * bsv[nf][0] + old.x);
                        float v1 = sp(x1 + dg * bsv[nf][1] + old.y);
                        *(float2*)&C[(size_t)row * Nc + col] = make_float2(v0, v1);
                        if (out2)
                            *(float2*)&out2[(size_t)row * Nc + col] = make_float2(v0, v1);
                    }
                }
            }
        }
    }
}

// ---------------- CSR aggregations (warp per node, no atomics) ----------------
__global__ void agg_max_kernel(const float* __restrict__ b_bond, float* __restrict__ out2) {
    int nid = blockIdx.x * 8 + (threadIdx.x >> 5);
    if (nid >= NN) return;
    int l = threadIdx.x & 31;
    int o0 = g_off[nid], o1 = g_off[nid + 1];
    const float4* PQ4 = (const float4*)g_PQ;
    float4 res;
    if (o1 > o0) {
        float4 m = make_float4(-FLT_MAX, -FLT_MAX, -FLT_MAX, -FLT_MAX);
        for (int i = o0; i < o1; i++) {
            int s = g_csr_src[i];
            m = max4(m, PQ4[(size_t)s * 64 + 32 + l]);
        }
        float4 p  = PQ4[(size_t)nid * 64 + l];
        float4 bb = ((const float4*)b_bond)[l];
        res = make_float4(sp(m.x + p.x + bb.x), sp(m.y + p.y + bb.y),
                          sp(m.z + p.z + bb.z), sp(m.w + p.w + bb.w));
    } else {
        res = make_float4(LN2F, LN2F, LN2F, LN2F);
    }
    ((float4*)g_hb)[(size_t)nid * 32 + l] = res;
    if (out2) ((float4*)out2)[(size_t)nid * 32 + l] = res;
}

__global__ void agg_sum_kernel() {
    int nid = blockIdx.x * 8 + (threadIdx.x >> 5);
    if (nid >= NN) return;
    int l = threadIdx.x & 31;
    int o0 = g_off[nid], o1 = g_off[nid + 1];
    const float4* ha4 = (const float4*)g_ha;
    const float4* hb4 = (const float4*)g_hb;
    float4 u = make_float4(0.f, 0.f, 0.f, 0.f);
    float4 t = make_float4(0.f, 0.f, 0.f, 0.f);
    float cge = 0.f;
    for (int i = o0; i < o1; i++) {
        int s = g_csr_src[i];
        int e = g_csr_eid[i];
        float4 av = ha4[(size_t)s * 32 + l];
        u.x += av.x; u.y += av.y; u.z += av.z; u.w += av.w;
        if (e < NN) {
            float4 bv = hb4[(size_t)e * 32 + l];
            t.x += bv.x; t.y += bv.y; t.z += bv.z; t.w += bv.w;
        } else cge += 1.f;
    }
    float cc = cge * LN2F;
    t.x += cc; t.y += cc; t.z += cc; t.w += cc;
    float4* X4 = (float4*)g_X;
    X4[(size_t)nid * 64 + l]      = u;
    X4[(size_t)nid * 64 + 32 + l] = t;
}

// ---------------- fused pool + readout ----------
__global__ void pool_readout_kernel(const float* __restrict__ Wr1, const float* __restrict__ br1,
                                    const float* __restrict__ Wr2, const float* __restrict__ br2,
                                    const float* __restrict__ Wr3, const float* __restrict__ br3,
                                    float* __restrict__ out) {
    __shared__ float pv[128];
    __shared__ float h1[64];
    __shared__ float h2[64];
    __shared__ float red[2];
    int g = blockIdx.x;
    int t = threadIdx.x;
    int s = g_gstart[g], e = g_gstart[g + 1];
    float sum = 0.f;
    for (int n = s; n < e; n++) sum += g_ha[(size_t)n * 128 + t];
    pv[t] = sum;
    __syncthreads();
    if (t < 64) {
        float a1 = br1[t];
#pragma unroll 8
        for (int k = 0; k < 128; k++) a1 += pv[k] * Wr1[k * 64 + t];
        h1[t] = sp(a1);
    }
    __syncthreads();
    if (t < 64) {
        float a2 = br2[t];
#pragma unroll 8
        for (int k = 0; k < 64; k++) a2 += h1[k] * Wr2[k * 64 + t];
        h2[t] = sp(a2);
    }
    __syncthreads();
    if (t < 64) {
        float v = h2[t] * Wr3[t];
#pragma unroll
        for (int o = 16; o > 0; o >>= 1) v += __shfl_down_sync(0xffffffffu, v, o);
        if ((t & 31) == 0) red[t >> 5] = v;
    }
    __syncthreads();
    if (t == 0) out[g] = red[0] + red[1] + br3[0];
}

__global__ void tail_hb_kernel(float* __restrict__ out_hb) {
    int t = blockIdx.x * blockDim.x + threadIdx.x;
    if (t >= (EE - NN) * 32) return;
    ((float4*)out_hb)[(size_t)NN * 32 + t] = make_float4(LN2F, LN2F, LN2F, LN2F);
}

// ---------------- launch ----------------
extern "C" void kernel_launch(void* const* d_in, const int* in_sizes, int n_in,
                              void* d_out, int out_size) {
    const int*   x_ids      = (const int*)d_in[0];
    const int*   edge_attr  = (const int*)d_in[1];
    const int*   edge_index = (const int*)d_in[2];
    const int*   batch      = (const int*)d_in[3];
    const float* emb_atom   = (const float*)d_in[4];
    const float* emb_bond   = (const float*)d_in[5];
    const float* W_bond     = (const float*)d_in[6];
    const float* b_bond     = (const float*)d_in[7];
    const float* W_msg      = (const float*)d_in[8];
    const float* b_msg      = (const float*)d_in[9];
    const float* W_edge     = (const float*)d_in[10];
    const float* b_edge     = (const float*)d_in[11];
    const float* W_r1       = (const float*)d_in[12];
    const float* b_r1       = (const float*)d_in[13];
    const float* W_r2       = (const float*)d_in[14];
    const float* b_r2       = (const float*)d_in[15];
    const float* W_r3       = (const float*)d_in[16];
    const float* b_r3       = (const float*)d_in[17];

    const int* src = edge_index;
    const int* dst = edge_index + EE;

    float* out_g  = (float*)d_out;
    float* out_ha = out_g + GG;
    float* out_hb = out_ha + (size_t)NN * EMB;

    void *p_deg, *p_fill, *p_ha, *p_hb, *p_PQ, *p_X, *p_comb, *p_wcat;
    cudaGetSymbolAddress(&p_deg,  g_deg);
    cudaGetSymbolAddress(&p_fill, g_fill);
    cudaGetSymbolAddress(&p_ha,   g_ha);
    cudaGetSymbolAddress(&p_hb,   g_hb);
    cudaGetSymbolAddress(&p_PQ,   g_PQ);
    cudaGetSymbolAddress(&p_X,    g_X);
    cudaGetSymbolAddress(&p_comb, g_comb);
    cudaGetSymbolAddress(&p_wcat, g_wcat);

    const int T = 256;
    int blk_n32 = (NN * 32 + T - 1) / T;
    int blk_n   = (NN + T - 1) / T;
    int blk_e   = (EE + T - 1) / T;
    int blk_w   = (NN + 7) / 8;
    int gm128   = (NN + 127) / 128;      // 782
    int nblk_scan = (NN + 1023) / 1024;

    // --- setup A (launches 1-5), first GEMM at slot 6 for ncu -s 5 -c 1 ---
    cudaMemsetAsync(p_deg,  0, NN * sizeof(int));                         // 1
    cudaMemsetAsync(p_fill, 0, NN * sizeof(int));                         // 2
    embed_sp_kernel<<<blk_n32, T>>>(emb_atom, x_ids, (float*)p_ha, NN);   // 3
    embed_sp_kernel<<<blk_n32, T>>>(emb_bond, edge_attr, (float*)p_hb, NN); // 4
    build_comb_kernel<<<(EMB * 2 * EMB + T - 1) / T, T>>>(W_bond);        // 5

    dim3 gr1(gm128, 2);
    gemm_tc<<<gr1, T>>>((const float*)p_hb, (const float*)p_comb, (float*)p_PQ,
                        NN, 128, 256, nullptr, nullptr, nullptr, nullptr); // 6 <- profiled

    // --- setup B (independent of GEMM) ---
    count_deg_kernel<<<blk_e, T>>>(dst);
    scan1_kernel<<<nblk_scan, 1024>>>();
    scan2_kernel<<<1, 32>>>(nblk_scan);
    scan3_kernel<<<blk_n, T>>>();
    fill_csr_kernel<<<blk_e, T>>>(src, dst);
    bounds_kernel<<<blk_n, T>>>(batch);
    build_wcat_kernel<<<(2 * EMB * EMB + T - 1) / T, T>>>(W_msg, W_edge);

    for (int pass = 0; pass < 2; pass++) {
        bool last = (pass == 1);
        if (pass > 0) {
            gemm_tc<<<gr1, T>>>((const float*)p_hb, (const float*)p_comb, (float*)p_PQ,
                                NN, 128, 256, nullptr, nullptr, nullptr, nullptr);
        }
        agg_max_kernel<<<blk_w, T>>>(b_bond, last ? out_hb : nullptr);
        agg_sum_kernel<<<blk_w, T>>>();
        dim3 gr2(gm128, 1);
        gemm_tc<<<gr2, T>>>((const float*)p_X, (const float*)p_wcat, (float*)p_ha,
                            NN, 256, 128, b_msg, b_edge, (const int*)p_deg,
                            last ? out_ha : nullptr);
    }

    pool_readout_kernel<<<GG, 128>>>(W_r1, b_r1, W_r2, b_r2, W_r3, b_r3, out_g);
    tail_hb_kernel<<<((EE - NN) * 32 + T - 1) / T, T>>>(out_hb);
}